// round 9
// baseline (speedup 1.0000x reference)
#include <cuda_runtime.h>
#include <cuda_bf16.h>
#include <math.h>
#include <stdint.h>

// ---------------------------------------------------------------------------
// DeepOHeat_ST: 4 trunk MLPs + branch MLP -> rank-64 CP outer product.
//
// Stage 1 (mlp_kernel): warp-private depth-4 cp.async weight pipeline,
//   no intra-layer block barriers.
// Stage 2 (gemm_kernel): fused operand build + bf16 split GEMM.
//   out = u @ w^T, 3-pass hi/lo split (residual ul*wl ~ 2^-16).
// ---------------------------------------------------------------------------

#define H 256
#define R 64
#define NF 64
#define WROW 36          // smem weight row stride (floats)
#define CHUNK_F (32 * WROW)          // floats per warp chunk buffer
#define WARP_BUF (4 * CHUNK_F)       // 4-deep ring per warp

__device__ float g_tn[4][64][64];            // [trunk][point][z]
__device__ float g_brn[8][64];               // [batch][z]

__device__ __forceinline__ float swish_f(float v) {
    return v / (1.0f + __expf(-v));
}
__device__ __forceinline__ uint32_t smem_u32(const void* p) {
    uint32_t a;
    asm("{ .reg .u64 t; cvta.to.shared.u64 t, %1; cvt.u32.u64 %0, t; }"
        : "=r"(a) : "l"(p));
    return a;
}

#define CP_ASYNC16(dst_u32, src_ptr) \
    asm volatile("cp.async.cg.shared.global [%0], [%1], 16;" \
                 :: "r"(dst_u32), "l"(src_ptr))
#define CP_COMMIT()  asm volatile("cp.async.commit_group;")
#define CP_WAIT(n)   asm volatile("cp.async.wait_group %0;" :: "n"(n))

// stage one 32-row x 32-col weight chunk into this warp's ring slot
__device__ __forceinline__ void stage_chunk(
    uint32_t buf, const float* __restrict__ W, int row0, int in_dim,
    int k0, int lane)
{
    #pragma unroll
    for (int s = 0; s < 8; s++) {
        int idx = lane + s * 32;               // 0..255
        int row = idx >> 3, kc = idx & 7;
        CP_ASYNC16(buf + (uint32_t)(row * WROW + kc * 4) * 4,
                   W + (size_t)(row0 + row) * in_dim + k0 + kc * 4);
    }
    CP_COMMIT();
}
__device__ __forceinline__ void wait_for(int rem) {
    if (rem >= 2)      { CP_WAIT(2); }
    else if (rem == 1) { CP_WAIT(1); }
    else               { CP_WAIT(0); }
}

// One 256-out layer over 4 points. Thread = neuron (tid), warp stages rows
// 32*warp. No block barriers inside.
__device__ __forceinline__ void layer256_wp(
    const float* __restrict__ W, float bias, int in_dim,
    const float (*actIn)[256], float (*actOut)[256],
    float* wbuf, uint32_t wbuf_a, int tid, bool do_swish)
{
    const int lane = tid & 31, warp = tid >> 5;
    const int row0 = warp * 32;
    const int nc = in_dim >> 5;
    float* mybuf = wbuf + warp * WARP_BUF;
    uint32_t mybuf_a = wbuf_a + warp * WARP_BUF * 4;

    stage_chunk(mybuf_a + 0 * CHUNK_F * 4, W, row0, in_dim, 0, lane);
    stage_chunk(mybuf_a + 1 * CHUNK_F * 4, W, row0, in_dim, 32, lane);
    stage_chunk(mybuf_a + 2 * CHUNK_F * 4, W, row0, in_dim, 64, lane);

    float acc[4] = {bias, bias, bias, bias};
    for (int c = 0; c < nc; c++) {
        wait_for(nc - 1 - c < 3 ? nc - 1 - c : 2);
        __syncwarp();
        const float* bp = mybuf + (c & 3) * CHUNK_F;
        #pragma unroll
        for (int kc = 0; kc < 8; kc++) {
            float4 w = *(const float4*)&bp[lane * WROW + kc * 4];
            #pragma unroll
            for (int p = 0; p < 4; p++) {
                const float* a = &actIn[p][c * 32 + kc * 4];
                acc[p] += w.x * a[0] + w.y * a[1] + w.z * a[2] + w.w * a[3];
            }
        }
        if (c + 3 < nc)
            stage_chunk(mybuf_a + ((c + 3) & 3) * CHUNK_F * 4,
                        W, row0, in_dim, (c + 3) * 32, lane);
    }
    #pragma unroll
    for (int p = 0; p < 4; p++)
        actOut[p][tid] = do_swish ? swish_f(acc[p]) : acc[p];
}

// Final 256 -> 64 linear layer. r = tid&63, pg = tid>>6.
// Warp stages rows (warp&1)*32 of W (4x redundant across warps, tiny).
__device__ __forceinline__ float layer_out_wp(
    const float* __restrict__ W, const float* __restrict__ bias,
    const float (*actIn)[256], float* wbuf, uint32_t wbuf_a, int tid)
{
    const int lane = tid & 31, warp = tid >> 5;
    const int row0 = (warp & 1) * 32;
    const int pg = tid >> 6;
    float* mybuf = wbuf + warp * WARP_BUF;
    uint32_t mybuf_a = wbuf_a + warp * WARP_BUF * 4;

    stage_chunk(mybuf_a + 0 * CHUNK_F * 4, W, row0, 256, 0, lane);
    stage_chunk(mybuf_a + 1 * CHUNK_F * 4, W, row0, 256, 32, lane);
    stage_chunk(mybuf_a + 2 * CHUNK_F * 4, W, row0, 256, 64, lane);

    float acc = bias[row0 + lane];
    #pragma unroll
    for (int c = 0; c < 8; c++) {
        wait_for(7 - c < 3 ? 7 - c : 2);
        __syncwarp();
        const float* bp = mybuf + (c & 3) * CHUNK_F;
        #pragma unroll
        for (int kc = 0; kc < 8; kc++) {
            float4 w = *(const float4*)&bp[lane * WROW + kc * 4];
            const float* a = &actIn[pg][c * 32 + kc * 4];
            acc += w.x * a[0] + w.y * a[1] + w.z * a[2] + w.w * a[3];
        }
        if (c + 3 < 8)
            stage_chunk(mybuf_a + ((c + 3) & 3) * CHUNK_F * 4,
                        W, row0, 256, (c + 3) * 32, lane);
    }
    return acc;
}

// ======================= Stage 1: batched MLPs =============================
// Blocks 0..47: trunks 0..2 (16 each, 4 points); 48..55: trunk 3; 56..57: branch.
__global__ __launch_bounds__(256, 1)
void mlp_kernel(
    const float* __restrict__ x1, const float* __restrict__ x2,
    const float* __restrict__ x3, const float* __restrict__ x4,
    const float* __restrict__ f,  const float* __restrict__ Bmat,
    const float* __restrict__ tW0, const float* __restrict__ tb0,
    const float* __restrict__ tW1, const float* __restrict__ tb1,
    const float* __restrict__ tW2, const float* __restrict__ tb2,
    const float* __restrict__ tW3, const float* __restrict__ tb3,
    const float* __restrict__ bW0, const float* __restrict__ bb0,
    const float* __restrict__ bW1, const float* __restrict__ bb1,
    const float* __restrict__ bW2, const float* __restrict__ bb2,
    const float* __restrict__ bW3, const float* __restrict__ bb3)
{
    extern __shared__ float smem[];
    float* wbuf = smem;                              // 8 warps x WARP_BUF
    float (*actA)[256] = (float (*)[256])(smem + 8 * WARP_BUF);
    float (*actB)[256] = actA + 4;
    const uint32_t wbuf_a = smem_u32(wbuf);
    const int bid = blockIdx.x;
    const int tid = threadIdx.x;

    if (bid < 56) {
        int d, n0;
        if (bid < 48) { d = bid >> 4; n0 = (bid & 15) << 2; }
        else          { d = 3;        n0 = (bid - 48) << 2; }
        const float* xp = (d == 0) ? x1 : (d == 1) ? x2 : (d == 2) ? x3 : x4;

        #pragma unroll
        for (int it = 0; it < 2; it++) {
            int idx = tid + it * 256;        // 0..511
            int p = idx >> 7, ff = idx & 127;
            float x = xp[n0 + p];
            actA[p][ff] = (ff < 64) ? cosf(x * Bmat[ff]) : sinf(x * Bmat[ff - 64]);
        }
        __syncthreads();

        layer256_wp(tW0 + (size_t)d * H * 128, tb0[d * H + tid], 128,
                    actA, actB, wbuf, wbuf_a, tid, true);
        __syncthreads();
        layer256_wp(tW1 + (size_t)d * H * 256, tb1[d * H + tid], 256,
                    actB, actA, wbuf, wbuf_a, tid, true);
        __syncthreads();
        layer256_wp(tW2 + (size_t)d * H * 256, tb2[d * H + tid], 256,
                    actA, actB, wbuf, wbuf_a, tid, true);
        __syncthreads();
        float v = layer_out_wp(tW3 + (size_t)d * R * 256, tb3 + d * R,
                               actB, wbuf, wbuf_a, tid);
        g_tn[d][n0 + (tid >> 6)][tid & 63] = v;
    } else {
        const int r0 = (bid - 56) << 2;
        #pragma unroll
        for (int it = 0; it < 4; it++) {
            int idx = tid + it * 256;        // 0..1023
            int p = idx >> 8, ff = idx & 255;
            actA[p][ff] = f[(r0 + p) * 256 + ff];
        }
        __syncthreads();

        layer256_wp(bW0, bb0[tid], 256, actA, actB, wbuf, wbuf_a, tid, true);
        __syncthreads();
        layer256_wp(bW1, bb1[tid], 256, actB, actA, wbuf, wbuf_a, tid, true);
        __syncthreads();
        layer256_wp(bW2, bb2[tid], 256, actA, actB, wbuf, wbuf_a, tid, true);
        __syncthreads();
        float v = layer_out_wp(bW3, bb3, actB, wbuf, wbuf_a, tid);
        g_brn[r0 + (tid >> 6)][tid & 63] = v;
    }
}

// ======================= Stage 2: fused pack + GEMM ========================
// CTA tile 128(M) x 128(N), K=128 (64 hi + 64 lo) built in-kernel from
// g_tn/g_brn. 3 passes of 4 k-steps realize the hi/lo split product.
// smem: A 32KB + B 32KB, XOR-swizzled 16B chunks -> conflict-free ldmatrix.
// 8 warps, 2(M) x 4(N), warp tile 64x32, atoms m16n8k16.
__device__ __forceinline__ void split8(
    const float* u, uint32_t* hw, uint32_t* lw)
{
    #pragma unroll
    for (int q = 0; q < 4; q++) {
        __nv_bfloat16 h0 = __float2bfloat16(u[2 * q]);
        __nv_bfloat16 h1 = __float2bfloat16(u[2 * q + 1]);
        float r0 = u[2 * q]     - __bfloat162float(h0);
        float r1 = u[2 * q + 1] - __bfloat162float(h1);
        __nv_bfloat16 l0 = __float2bfloat16(r0);
        __nv_bfloat16 l1 = __float2bfloat16(r1);
        hw[q] = (uint32_t)__bfloat16_as_ushort(h0)
              | ((uint32_t)__bfloat16_as_ushort(h1) << 16);
        lw[q] = (uint32_t)__bfloat16_as_ushort(l0)
              | ((uint32_t)__bfloat16_as_ushort(l1) << 16);
    }
}

__global__ __launch_bounds__(256, 2)
void gemm_kernel(float* __restrict__ out)
{
    extern __shared__ __align__(128) char gsm[];
    char* As = gsm;            // [128 rows][256 B]
    char* Bs = gsm + 32768;    // [128 rows][256 B]
    const int tid  = threadIdx.x;
    const int wid  = tid >> 5;
    const int lane = tid & 31;
    const int m0 = blockIdx.y * 128;
    const int n0 = blockIdx.x * 128;

    // ---- build A tile: u[m,z] = t1[i,z]*t2[j,z], hi/lo split ----
    #pragma unroll
    for (int it = 0; it < 4; it++) {
        int item = tid + it * 256;          // 0..1023
        int r = item >> 3, zc = item & 7, z0 = zc * 8;
        int i = (m0 + r) >> 6, j = r & 63;
        const float* t1 = g_tn[0][i];
        const float* t2 = g_tn[1][j];
        float4 a0 = *(const float4*)&t1[z0], a1 = *(const float4*)&t1[z0 + 4];
        float4 c0 = *(const float4*)&t2[z0], c1 = *(const float4*)&t2[z0 + 4];
        float u[8] = {a0.x * c0.x, a0.y * c0.y, a0.z * c0.z, a0.w * c0.w,
                      a1.x * c1.x, a1.y * c1.y, a1.z * c1.z, a1.w * c1.w};
        uint32_t hw[4], lw[4];
        split8(u, hw, lw);
        *(uint4*)(As + r * 256 + ((zc ^ (r & 7)) << 4)) =
            make_uint4(hw[0], hw[1], hw[2], hw[3]);
        *(uint4*)(As + r * 256 + (((zc + 8) ^ (r & 7)) << 4)) =
            make_uint4(lw[0], lw[1], lw[2], lw[3]);
    }
    // ---- build B tile: w[n,z] = br[b,z]*t3[k,z]*t4[l,z] ----
    #pragma unroll
    for (int it = 0; it < 4; it++) {
        int item = tid + it * 256;
        int c = item >> 3, zc = item & 7, z0 = zc * 8;
        int n = n0 + c;
        int b = n >> 11, k = (n >> 5) & 63, l = n & 31;
        const float* br = g_brn[b];
        const float* t3 = g_tn[2][k];
        const float* t4 = g_tn[3][l];
        float4 p0 = *(const float4*)&br[z0], p1 = *(const float4*)&br[z0 + 4];
        float4 q0 = *(const float4*)&t3[z0], q1 = *(const float4*)&t3[z0 + 4];
        float4 r0 = *(const float4*)&t4[z0], r1 = *(const float4*)&t4[z0 + 4];
        float u[8] = {p0.x * q0.x * r0.x, p0.y * q0.y * r0.y,
                      p0.z * q0.z * r0.z, p0.w * q0.w * r0.w,
                      p1.x * q1.x * r1.x, p1.y * q1.y * r1.y,
                      p1.z * q1.z * r1.z, p1.w * q1.w * r1.w};
        uint32_t hw[4], lw[4];
        split8(u, hw, lw);
        *(uint4*)(Bs + c * 256 + ((zc ^ (c & 7)) << 4)) =
            make_uint4(hw[0], hw[1], hw[2], hw[3]);
        *(uint4*)(Bs + c * 256 + (((zc + 8) ^ (c & 7)) << 4)) =
            make_uint4(lw[0], lw[1], lw[2], lw[3]);
    }
    __syncthreads();

    const int warp_m = wid & 1;          // 0..1  (64 rows each)
    const int warp_n = wid >> 1;         // 0..3  (32 cols each)
    const uint32_t a_base = smem_u32(As);
    const uint32_t b_base = smem_u32(Bs);

    float acc[4][4][4];
    #pragma unroll
    for (int am = 0; am < 4; am++)
        #pragma unroll
        for (int bn = 0; bn < 4; bn++)
            #pragma unroll
            for (int q = 0; q < 4; q++) acc[am][bn][q] = 0.0f;

    // 3 passes: (A hi, B hi), (A lo, B hi), (A hi, B lo)
    #pragma unroll
    for (int pass = 0; pass < 3; pass++) {
        const int a_off = (pass == 1) ? 4 : 0;   // k-step offset (16 elems)
        const int b_off = (pass == 2) ? 4 : 0;
        #pragma unroll
        for (int ks = 0; ks < 4; ks++) {
            uint32_t a[4][4], b[4][2];
            #pragma unroll
            for (int am = 0; am < 4; am++) {
                int row = warp_m * 64 + am * 16 + (lane & 15);
                int kc  = (a_off + ks) * 2 + (lane >> 4);
                uint32_t addr = a_base + row * 256 + ((kc ^ (row & 7)) << 4);
                asm volatile("ldmatrix.sync.aligned.m8n8.x4.shared.b16 {%0,%1,%2,%3}, [%4];"
                             : "=r"(a[am][0]), "=r"(a[am][1]),
                               "=r"(a[am][2]), "=r"(a[am][3]) : "r"(addr));
            }
            #pragma unroll
            for (int bn = 0; bn < 4; bn++) {
                int row = warp_n * 32 + bn * 8 + (lane & 7);
                int kc  = (b_off + ks) * 2 + ((lane >> 3) & 1);
                uint32_t addr = b_base + row * 256 + ((kc ^ (row & 7)) << 4);
                asm volatile("ldmatrix.sync.aligned.m8n8.x2.shared.b16 {%0,%1}, [%2];"
                             : "=r"(b[bn][0]), "=r"(b[bn][1]) : "r"(addr));
            }
            #pragma unroll
            for (int am = 0; am < 4; am++)
                #pragma unroll
                for (int bn = 0; bn < 4; bn++)
                    asm volatile(
                        "mma.sync.aligned.m16n8k16.row.col.f32.bf16.bf16.f32 "
                        "{%0,%1,%2,%3}, {%4,%5,%6,%7}, {%8,%9}, {%0,%1,%2,%3};"
                        : "+f"(acc[am][bn][0]), "+f"(acc[am][bn][1]),
                          "+f"(acc[am][bn][2]), "+f"(acc[am][bn][3])
                        : "r"(a[am][0]), "r"(a[am][1]), "r"(a[am][2]), "r"(a[am][3]),
                          "r"(b[bn][0]), "r"(b[bn][1]));
        }
    }

    // ---- epilogue: out[(((b*64+i)*64+j)*64+k)*32+l] ----
    #pragma unroll
    for (int am = 0; am < 4; am++) {
        #pragma unroll
        for (int bn = 0; bn < 4; bn++) {
            int mg = m0 + warp_m * 64 + am * 16 + (lane >> 2);
            int ng = n0 + warp_n * 32 + bn * 8 + (lane & 3) * 2;
            int bi = ng >> 11, rem = ng & 2047;
            {
                int i = mg >> 6, j = mg & 63;
                float* p = out + (((size_t)bi * 64 + i) * 64 + j) * 2048 + rem;
                *(float2*)p = make_float2(acc[am][bn][0], acc[am][bn][1]);
            }
            {
                int mg2 = mg + 8;
                int i = mg2 >> 6, j = mg2 & 63;
                float* p = out + (((size_t)bi * 64 + i) * 64 + j) * 2048 + rem;
                *(float2*)p = make_float2(acc[am][bn][2], acc[am][bn][3]);
            }
        }
    }
}

// ======================= launch ============================================
#define MLP_SMEM (8 * WARP_BUF * 4 + 2 * 4 * 256 * 4)

extern "C" void kernel_launch(void* const* d_in, const int* in_sizes, int n_in,
                              void* d_out, int out_size)
{
    const float* x1  = (const float*)d_in[0];
    const float* x2  = (const float*)d_in[1];
    const float* x3  = (const float*)d_in[2];
    const float* x4  = (const float*)d_in[3];
    const float* f   = (const float*)d_in[4];
    const float* Bm  = (const float*)d_in[5];
    const float* tW0 = (const float*)d_in[6];
    const float* tb0 = (const float*)d_in[7];
    const float* tW1 = (const float*)d_in[8];
    const float* tb1 = (const float*)d_in[9];
    const float* tW2 = (const float*)d_in[10];
    const float* tb2 = (const float*)d_in[11];
    const float* tW3 = (const float*)d_in[12];
    const float* tb3 = (const float*)d_in[13];
    const float* bW0 = (const float*)d_in[14];
    const float* bb0 = (const float*)d_in[15];
    const float* bW1 = (const float*)d_in[16];
    const float* bb1 = (const float*)d_in[17];
    const float* bW2 = (const float*)d_in[18];
    const float* bb2 = (const float*)d_in[19];
    const float* bW3 = (const float*)d_in[20];
    const float* bb3 = (const float*)d_in[21];

    cudaFuncSetAttribute(mlp_kernel,
                         cudaFuncAttributeMaxDynamicSharedMemorySize, MLP_SMEM);
    mlp_kernel<<<58, 256, MLP_SMEM>>>(x1, x2, x3, x4, f, Bm,
                                      tW0, tb0, tW1, tb1, tW2, tb2, tW3, tb3,
                                      bW0, bb0, bW1, bb1, bW2, bb2, bW3, bb3);

    cudaFuncSetAttribute(gemm_kernel,
                         cudaFuncAttributeMaxDynamicSharedMemorySize, 65536);
    dim3 grid(128, 32);
    gemm_kernel<<<grid, 256, 65536>>>((float*)d_out);
}

// round 10
// speedup vs baseline: 1.3079x; 1.3079x over previous
#include <cuda_runtime.h>
#include <cuda_bf16.h>
#include <math.h>
#include <stdint.h>

// ---------------------------------------------------------------------------
// DeepOHeat_ST: 4 trunk MLPs + branch MLP -> rank-64 CP outer product.
//
// Stage 1 (mlp_kernel): warp-private depth-4 cp.async weight pipeline.
// Stage 2 (pack_kernel): bf16 hi/lo split operands  A'=[uh|ul], B'=[wh|wl]
// Stage 3 (gemm_kernel): out = u @ w^T via mma.sync bf16, fp32 accum.
//   cp.async tile staging; per k-chunk hi/lo fragments loaded once,
//   3 MMA combos (uh*wh + ul*wh + uh*wl) into shared accumulators.
// ---------------------------------------------------------------------------

#define H 256
#define R 64
#define NF 64
#define WROW 36          // smem weight row stride (floats)
#define CHUNK_F (32 * WROW)          // floats per warp chunk buffer
#define WARP_BUF (4 * CHUNK_F)       // 4-deep ring per warp

__device__ float g_tn[4][64][64];            // [trunk][point][z]
__device__ float g_brn[8][64];               // [batch][z]
__device__ __nv_bfloat16 g_A[4096 * 128];    // [m][k]  k: 0..63 hi, 64..127 lo
__device__ __nv_bfloat16 g_B[16384 * 128];   // [n][k]

__device__ __forceinline__ float swish_f(float v) {
    return v / (1.0f + __expf(-v));
}
__device__ __forceinline__ uint32_t smem_u32(const void* p) {
    uint32_t a;
    asm("{ .reg .u64 t; cvta.to.shared.u64 t, %1; cvt.u32.u64 %0, t; }"
        : "=r"(a) : "l"(p));
    return a;
}

#define CP_ASYNC16(dst_u32, src_ptr) \
    asm volatile("cp.async.cg.shared.global [%0], [%1], 16;" \
                 :: "r"(dst_u32), "l"(src_ptr))
#define CP_COMMIT()  asm volatile("cp.async.commit_group;")
#define CP_WAIT(n)   asm volatile("cp.async.wait_group %0;" :: "n"(n))

// ======================= Stage 1: batched MLPs =============================
__device__ __forceinline__ void stage_chunk(
    uint32_t buf, const float* __restrict__ W, int row0, int in_dim,
    int k0, int lane)
{
    #pragma unroll
    for (int s = 0; s < 8; s++) {
        int idx = lane + s * 32;               // 0..255
        int row = idx >> 3, kc = idx & 7;
        CP_ASYNC16(buf + (uint32_t)(row * WROW + kc * 4) * 4,
                   W + (size_t)(row0 + row) * in_dim + k0 + kc * 4);
    }
    CP_COMMIT();
}
__device__ __forceinline__ void wait_for(int rem) {
    if (rem >= 2)      { CP_WAIT(2); }
    else if (rem == 1) { CP_WAIT(1); }
    else               { CP_WAIT(0); }
}

__device__ __forceinline__ void layer256_wp(
    const float* __restrict__ W, float bias, int in_dim,
    const float (*actIn)[256], float (*actOut)[256],
    float* wbuf, uint32_t wbuf_a, int tid, bool do_swish)
{
    const int lane = tid & 31, warp = tid >> 5;
    const int row0 = warp * 32;
    const int nc = in_dim >> 5;
    float* mybuf = wbuf + warp * WARP_BUF;
    uint32_t mybuf_a = wbuf_a + warp * WARP_BUF * 4;

    stage_chunk(mybuf_a + 0 * CHUNK_F * 4, W, row0, in_dim, 0, lane);
    stage_chunk(mybuf_a + 1 * CHUNK_F * 4, W, row0, in_dim, 32, lane);
    stage_chunk(mybuf_a + 2 * CHUNK_F * 4, W, row0, in_dim, 64, lane);

    float acc[4] = {bias, bias, bias, bias};
    for (int c = 0; c < nc; c++) {
        wait_for(nc - 1 - c < 3 ? nc - 1 - c : 2);
        __syncwarp();
        const float* bp = mybuf + (c & 3) * CHUNK_F;
        #pragma unroll
        for (int kc = 0; kc < 8; kc++) {
            float4 w = *(const float4*)&bp[lane * WROW + kc * 4];
            #pragma unroll
            for (int p = 0; p < 4; p++) {
                const float* a = &actIn[p][c * 32 + kc * 4];
                acc[p] += w.x * a[0] + w.y * a[1] + w.z * a[2] + w.w * a[3];
            }
        }
        if (c + 3 < nc)
            stage_chunk(mybuf_a + ((c + 3) & 3) * CHUNK_F * 4,
                        W, row0, in_dim, (c + 3) * 32, lane);
    }
    #pragma unroll
    for (int p = 0; p < 4; p++)
        actOut[p][tid] = do_swish ? swish_f(acc[p]) : acc[p];
}

__device__ __forceinline__ float layer_out_wp(
    const float* __restrict__ W, const float* __restrict__ bias,
    const float (*actIn)[256], float* wbuf, uint32_t wbuf_a, int tid)
{
    const int lane = tid & 31, warp = tid >> 5;
    const int row0 = (warp & 1) * 32;
    const int pg = tid >> 6;
    float* mybuf = wbuf + warp * WARP_BUF;
    uint32_t mybuf_a = wbuf_a + warp * WARP_BUF * 4;

    stage_chunk(mybuf_a + 0 * CHUNK_F * 4, W, row0, 256, 0, lane);
    stage_chunk(mybuf_a + 1 * CHUNK_F * 4, W, row0, 256, 32, lane);
    stage_chunk(mybuf_a + 2 * CHUNK_F * 4, W, row0, 256, 64, lane);

    float acc = bias[row0 + lane];
    #pragma unroll
    for (int c = 0; c < 8; c++) {
        wait_for(7 - c < 3 ? 7 - c : 2);
        __syncwarp();
        const float* bp = mybuf + (c & 3) * CHUNK_F;
        #pragma unroll
        for (int kc = 0; kc < 8; kc++) {
            float4 w = *(const float4*)&bp[lane * WROW + kc * 4];
            const float* a = &actIn[pg][c * 32 + kc * 4];
            acc += w.x * a[0] + w.y * a[1] + w.z * a[2] + w.w * a[3];
        }
        if (c + 3 < 8)
            stage_chunk(mybuf_a + ((c + 3) & 3) * CHUNK_F * 4,
                        W, row0, 256, (c + 3) * 32, lane);
    }
    return acc;
}

__global__ __launch_bounds__(256, 1)
void mlp_kernel(
    const float* __restrict__ x1, const float* __restrict__ x2,
    const float* __restrict__ x3, const float* __restrict__ x4,
    const float* __restrict__ f,  const float* __restrict__ Bmat,
    const float* __restrict__ tW0, const float* __restrict__ tb0,
    const float* __restrict__ tW1, const float* __restrict__ tb1,
    const float* __restrict__ tW2, const float* __restrict__ tb2,
    const float* __restrict__ tW3, const float* __restrict__ tb3,
    const float* __restrict__ bW0, const float* __restrict__ bb0,
    const float* __restrict__ bW1, const float* __restrict__ bb1,
    const float* __restrict__ bW2, const float* __restrict__ bb2,
    const float* __restrict__ bW3, const float* __restrict__ bb3)
{
    extern __shared__ float smem[];
    float* wbuf = smem;                              // 8 warps x WARP_BUF
    float (*actA)[256] = (float (*)[256])(smem + 8 * WARP_BUF);
    float (*actB)[256] = actA + 4;
    const uint32_t wbuf_a = smem_u32(wbuf);
    const int bid = blockIdx.x;
    const int tid = threadIdx.x;

    if (bid < 56) {
        int d, n0;
        if (bid < 48) { d = bid >> 4; n0 = (bid & 15) << 2; }
        else          { d = 3;        n0 = (bid - 48) << 2; }
        const float* xp = (d == 0) ? x1 : (d == 1) ? x2 : (d == 2) ? x3 : x4;

        #pragma unroll
        for (int it = 0; it < 2; it++) {
            int idx = tid + it * 256;        // 0..511
            int p = idx >> 7, ff = idx & 127;
            float x = xp[n0 + p];
            actA[p][ff] = (ff < 64) ? cosf(x * Bmat[ff]) : sinf(x * Bmat[ff - 64]);
        }
        __syncthreads();

        layer256_wp(tW0 + (size_t)d * H * 128, tb0[d * H + tid], 128,
                    actA, actB, wbuf, wbuf_a, tid, true);
        __syncthreads();
        layer256_wp(tW1 + (size_t)d * H * 256, tb1[d * H + tid], 256,
                    actB, actA, wbuf, wbuf_a, tid, true);
        __syncthreads();
        layer256_wp(tW2 + (size_t)d * H * 256, tb2[d * H + tid], 256,
                    actA, actB, wbuf, wbuf_a, tid, true);
        __syncthreads();
        float v = layer_out_wp(tW3 + (size_t)d * R * 256, tb3 + d * R,
                               actB, wbuf, wbuf_a, tid);
        g_tn[d][n0 + (tid >> 6)][tid & 63] = v;
    } else {
        const int r0 = (bid - 56) << 2;
        #pragma unroll
        for (int it = 0; it < 4; it++) {
            int idx = tid + it * 256;        // 0..1023
            int p = idx >> 8, ff = idx & 255;
            actA[p][ff] = f[(r0 + p) * 256 + ff];
        }
        __syncthreads();

        layer256_wp(bW0, bb0[tid], 256, actA, actB, wbuf, wbuf_a, tid, true);
        __syncthreads();
        layer256_wp(bW1, bb1[tid], 256, actB, actA, wbuf, wbuf_a, tid, true);
        __syncthreads();
        layer256_wp(bW2, bb2[tid], 256, actA, actB, wbuf, wbuf_a, tid, true);
        __syncthreads();
        float v = layer_out_wp(bW3, bb3, actB, wbuf, wbuf_a, tid);
        g_brn[r0 + (tid >> 6)][tid & 63] = v;
    }
}

// ======================= Stage 2: bf16 split pack ==========================
__device__ __forceinline__ void split_store(__nv_bfloat16* row, int z0, float4 u) {
    float uv[4] = {u.x, u.y, u.z, u.w};
    __nv_bfloat16 h[4], lo[4];
    #pragma unroll
    for (int q = 0; q < 4; q++) {
        h[q]  = __float2bfloat16(uv[q]);
        lo[q] = __float2bfloat16(uv[q] - __bfloat162float(h[q]));
    }
    *(__nv_bfloat162*)(row + z0)          = __nv_bfloat162(h[0], h[1]);
    *(__nv_bfloat162*)(row + z0 + 2)      = __nv_bfloat162(h[2], h[3]);
    *(__nv_bfloat162*)(row + 64 + z0)     = __nv_bfloat162(lo[0], lo[1]);
    *(__nv_bfloat162*)(row + 64 + z0 + 2) = __nv_bfloat162(lo[2], lo[3]);
}

__global__ void pack_kernel()
{
    int id = blockIdx.x * 256 + threadIdx.x;
    if (id < 65536) {
        int m = id >> 4, z0 = (id & 15) << 2;
        int i = m >> 6, j = m & 63;
        float4 a = *(const float4*)&g_tn[0][i][z0];
        float4 c = *(const float4*)&g_tn[1][j][z0];
        split_store(g_A + (size_t)m * 128, z0,
                    make_float4(a.x * c.x, a.y * c.y, a.z * c.z, a.w * c.w));
    } else {
        id -= 65536;                       // [0, 262144)
        int n = id >> 4, z0 = (id & 15) << 2;
        int b = n >> 11, k = (n >> 5) & 63, l = n & 31;
        float4 p = *(const float4*)&g_brn[b][z0];
        float4 q = *(const float4*)&g_tn[2][k][z0];
        float4 r = *(const float4*)&g_tn[3][l][z0];
        split_store(g_B + (size_t)n * 128, z0,
                    make_float4(p.x * q.x * r.x, p.y * q.y * r.y,
                                p.z * q.z * r.z, p.w * q.w * r.w));
    }
}

// ======================= Stage 3: mma.sync bf16 GEMM =======================
// CTA tile 128(M) x 128(N), K=128. cp.async tile staging (L1 bypass).
// Per k-chunk: load a_hi/a_lo (x4) + b_hi/b_lo (x2) fragments ONCE,
// issue 3 MMA combos into shared accumulators.
// smem XOR-swizzled 16B chunks -> conflict-free ldmatrix.
__global__ __launch_bounds__(256, 2)
void gemm_kernel(float* __restrict__ out)
{
    extern __shared__ __align__(128) char gsm[];
    char* As = gsm;            // [128 rows][256 B]
    char* Bs = gsm + 32768;    // [128 rows][256 B]
    const int tid  = threadIdx.x;
    const int wid  = tid >> 5;
    const int lane = tid & 31;
    const int m0 = blockIdx.y * 128;
    const int n0 = blockIdx.x * 128;

    // ---- stage tiles via cp.async (bypasses RF/L1) ----
    const __nv_bfloat16* Ag = g_A + (size_t)m0 * 128;
    const __nv_bfloat16* Bg = g_B + (size_t)n0 * 128;
    const uint32_t as_u = smem_u32(As);
    const uint32_t bs_u = smem_u32(Bs);
    #pragma unroll
    for (int it = 0; it < 8; it++) {
        int idx = tid + it * 256;        // 0..2047
        int row = idx >> 4;
        int kc  = idx & 15;
        CP_ASYNC16(as_u + row * 256 + ((kc ^ (row & 7)) << 4),
                   Ag + row * 128 + kc * 8);
    }
    #pragma unroll
    for (int it = 0; it < 8; it++) {
        int idx = tid + it * 256;
        int row = idx >> 4;
        int kc  = idx & 15;
        CP_ASYNC16(bs_u + row * 256 + ((kc ^ (row & 7)) << 4),
                   Bg + row * 128 + kc * 8);
    }
    CP_COMMIT();
    CP_WAIT(0);
    __syncthreads();

    const int warp_m = wid & 1;          // 0..1  (64 rows each)
    const int warp_n = wid >> 1;         // 0..3  (32 cols each)

    float acc[4][4][4];
    #pragma unroll
    for (int am = 0; am < 4; am++)
        #pragma unroll
        for (int bn = 0; bn < 4; bn++)
            #pragma unroll
            for (int q = 0; q < 4; q++) acc[am][bn][q] = 0.0f;

    #pragma unroll
    for (int ks = 0; ks < 4; ks++) {
        // B fragments for this k-chunk: hi (kc = ks*2 + ...) and lo (+8)
        uint32_t bh[4][2], bl[4][2];
        #pragma unroll
        for (int bn = 0; bn < 4; bn++) {
            int row = warp_n * 32 + bn * 8 + (lane & 7);
            int kch = ks * 2 + ((lane >> 3) & 1);
            int kcl = kch + 8;
            uint32_t ah_ = as_u; (void)ah_;
            uint32_t addr_h = bs_u + row * 256 + ((kch ^ (row & 7)) << 4);
            uint32_t addr_l = bs_u + row * 256 + ((kcl ^ (row & 7)) << 4);
            asm volatile("ldmatrix.sync.aligned.m8n8.x2.shared.b16 {%0,%1}, [%2];"
                         : "=r"(bh[bn][0]), "=r"(bh[bn][1]) : "r"(addr_h));
            asm volatile("ldmatrix.sync.aligned.m8n8.x2.shared.b16 {%0,%1}, [%2];"
                         : "=r"(bl[bn][0]), "=r"(bl[bn][1]) : "r"(addr_l));
        }
        #pragma unroll
        for (int am = 0; am < 4; am++) {
            int row = warp_m * 64 + am * 16 + (lane & 15);
            int kch = ks * 2 + (lane >> 4);
            int kcl = kch + 8;
            uint32_t ah[4], al[4];
            uint32_t addr_h = as_u + row * 256 + ((kch ^ (row & 7)) << 4);
            uint32_t addr_l = as_u + row * 256 + ((kcl ^ (row & 7)) << 4);
            asm volatile("ldmatrix.sync.aligned.m8n8.x4.shared.b16 {%0,%1,%2,%3}, [%4];"
                         : "=r"(ah[0]), "=r"(ah[1]), "=r"(ah[2]), "=r"(ah[3])
                         : "r"(addr_h));
            asm volatile("ldmatrix.sync.aligned.m8n8.x4.shared.b16 {%0,%1,%2,%3}, [%4];"
                         : "=r"(al[0]), "=r"(al[1]), "=r"(al[2]), "=r"(al[3])
                         : "r"(addr_l));
            #pragma unroll
            for (int bn = 0; bn < 4; bn++) {
                asm volatile(
                    "mma.sync.aligned.m16n8k16.row.col.f32.bf16.bf16.f32 "
                    "{%0,%1,%2,%3}, {%4,%5,%6,%7}, {%8,%9}, {%0,%1,%2,%3};"
                    : "+f"(acc[am][bn][0]), "+f"(acc[am][bn][1]),
                      "+f"(acc[am][bn][2]), "+f"(acc[am][bn][3])
                    : "r"(ah[0]), "r"(ah[1]), "r"(ah[2]), "r"(ah[3]),
                      "r"(bh[bn][0]), "r"(bh[bn][1]));
                asm volatile(
                    "mma.sync.aligned.m16n8k16.row.col.f32.bf16.bf16.f32 "
                    "{%0,%1,%2,%3}, {%4,%5,%6,%7}, {%8,%9}, {%0,%1,%2,%3};"
                    : "+f"(acc[am][bn][0]), "+f"(acc[am][bn][1]),
                      "+f"(acc[am][bn][2]), "+f"(acc[am][bn][3])
                    : "r"(al[0]), "r"(al[1]), "r"(al[2]), "r"(al[3]),
                      "r"(bh[bn][0]), "r"(bh[bn][1]));
                asm volatile(
                    "mma.sync.aligned.m16n8k16.row.col.f32.bf16.bf16.f32 "
                    "{%0,%1,%2,%3}, {%4,%5,%6,%7}, {%8,%9}, {%0,%1,%2,%3};"
                    : "+f"(acc[am][bn][0]), "+f"(acc[am][bn][1]),
                      "+f"(acc[am][bn][2]), "+f"(acc[am][bn][3])
                    : "r"(ah[0]), "r"(ah[1]), "r"(ah[2]), "r"(ah[3]),
                      "r"(bl[bn][0]), "r"(bl[bn][1]));
            }
        }
    }

    // ---- epilogue: out[(((b*64+i)*64+j)*64+k)*32+l] ----
    #pragma unroll
    for (int am = 0; am < 4; am++) {
        #pragma unroll
        for (int bn = 0; bn < 4; bn++) {
            int mg = m0 + warp_m * 64 + am * 16 + (lane >> 2);
            int ng = n0 + warp_n * 32 + bn * 8 + (lane & 3) * 2;
            int bi = ng >> 11, rem = ng & 2047;
            {
                int i = mg >> 6, j = mg & 63;
                float* p = out + (((size_t)bi * 64 + i) * 64 + j) * 2048 + rem;
                *(float2*)p = make_float2(acc[am][bn][0], acc[am][bn][1]);
            }
            {
                int mg2 = mg + 8;
                int i = mg2 >> 6, j = mg2 & 63;
                float* p = out + (((size_t)bi * 64 + i) * 64 + j) * 2048 + rem;
                *(float2*)p = make_float2(acc[am][bn][2], acc[am][bn][3]);
            }
        }
    }
}

// ======================= launch ============================================
#define MLP_SMEM (8 * WARP_BUF * 4 + 2 * 4 * 256 * 4)

extern "C" void kernel_launch(void* const* d_in, const int* in_sizes, int n_in,
                              void* d_out, int out_size)
{
    const float* x1  = (const float*)d_in[0];
    const float* x2  = (const float*)d_in[1];
    const float* x3  = (const float*)d_in[2];
    const float* x4  = (const float*)d_in[3];
    const float* f   = (const float*)d_in[4];
    const float* Bm  = (const float*)d_in[5];
    const float* tW0 = (const float*)d_in[6];
    const float* tb0 = (const float*)d_in[7];
    const float* tW1 = (const float*)d_in[8];
    const float* tb1 = (const float*)d_in[9];
    const float* tW2 = (const float*)d_in[10];
    const float* tb2 = (const float*)d_in[11];
    const float* tW3 = (const float*)d_in[12];
    const float* tb3 = (const float*)d_in[13];
    const float* bW0 = (const float*)d_in[14];
    const float* bb0 = (const float*)d_in[15];
    const float* bW1 = (const float*)d_in[16];
    const float* bb1 = (const float*)d_in[17];
    const float* bW2 = (const float*)d_in[18];
    const float* bb2 = (const float*)d_in[19];
    const float* bW3 = (const float*)d_in[20];
    const float* bb3 = (const float*)d_in[21];

    cudaFuncSetAttribute(mlp_kernel,
                         cudaFuncAttributeMaxDynamicSharedMemorySize, MLP_SMEM);
    mlp_kernel<<<58, 256, MLP_SMEM>>>(x1, x2, x3, x4, f, Bm,
                                      tW0, tb0, tW1, tb1, tW2, tb2, tW3, tb3,
                                      bW0, bb0, bW1, bb1, bW2, bb2, bW3, bb3);

    pack_kernel<<<1280, 256>>>();

    cudaFuncSetAttribute(gemm_kernel,
                         cudaFuncAttributeMaxDynamicSharedMemorySize, 65536);
    dim3 grid(128, 32);
    gemm_kernel<<<grid, 256, 65536>>>((float*)d_out);
}